// round 3
// baseline (speedup 1.0000x reference)
#include <cuda_runtime.h>

// Problem constants (AttCnn): B=16, NF=64, EC=3, H=W=256
#define HW_   65536           // H*W
#define B_    16
#define NF_   64
#define EC_   3
#define NF1_  8
#define NF2_  16
#define PAIRS_TOTAL (B_ * HW_ / 2)   // 524288 pixel pairs
#define TPB_  256

typedef unsigned long long u64;

__device__ __forceinline__ u64 pk2(float x, float y) {
    u64 r; asm("mov.b64 %0, {%1, %2};" : "=l"(r) : "f"(x), "f"(y)); return r;
}
__device__ __forceinline__ void unpk2(u64 p, float& x, float& y) {
    asm("mov.b64 {%0, %1}, %2;" : "=f"(x), "=f"(y) : "l"(p));
}
// Blackwell packed fp32x2 FMA / ADD (sm_103a). Lanewise bit-identical to
// scalar fma.rn.f32 / add.rn.f32 — safe for bit-matching a scalar reference.
__device__ __forceinline__ u64 fma2(u64 a, u64 b, u64 c) {
    u64 d; asm("fma.rn.f32x2 %0, %1, %2, %3;" : "=l"(d) : "l"(a), "l"(b), "l"(c)); return d;
}
__device__ __forceinline__ u64 add2(u64 a, u64 b) {
    u64 d; asm("add.rn.f32x2 %0, %1, %2;" : "=l"(d) : "l"(a), "l"(b)); return d;
}

__device__ __forceinline__ float leaky(float x) {
    // where(x>=0, x, 0.2x): for x>=0 returns x exactly; for x<0 returns rn(0.2*x).
    return fmaxf(x, 0.0f) + 0.2f * fminf(x, 0.0f);
}

__global__ void __launch_bounds__(TPB_)
attcnn_kernel(const float* __restrict__ fm,   // [B,NF,H,W]
              const float* __restrict__ ex,   // [B,EC,H,W]
              const float* __restrict__ w1,   // [NF1,EC]
              const float* __restrict__ b1,   // [NF1]
              const float* __restrict__ w2,   // [NF2,NF1]
              const float* __restrict__ b2,   // [NF2]
              const float* __restrict__ wm,   // [NF,NF2]
              const float* __restrict__ bm,   // [NF]
              const float* __restrict__ wa,   // [NF,NF2]
              const float* __restrict__ ba,   // [NF]
              float* __restrict__ out)        // [B,NF,H,W]
{
    // ---- shared weights (full fp32) ----
    __shared__ float s_w1[NF1_ * EC_];
    __shared__ float s_b1[NF1_];
    __shared__ float s_w2[NF2_ * NF1_];
    __shared__ float s_b2[NF2_];
    __shared__ __align__(16) float2 s_wm[NF_ * NF2_];   // (w,w) duplicated pairs
    __shared__ __align__(16) float2 s_wa[NF_ * NF2_];
    __shared__ __align__(16) float4 s_bma[NF_];         // (bm,bm,ba,ba)

    const int t = threadIdx.x;
    if (t < NF1_ * EC_)  s_w1[t] = w1[t];
    if (t < NF1_)        s_b1[t] = b1[t];
    if (t < NF2_ * NF1_) s_w2[t] = w2[t];
    if (t < NF2_)        s_b2[t] = b2[t];
    for (int i = t; i < NF_ * NF2_; i += TPB_) {
        float vm = wm[i]; s_wm[i] = make_float2(vm, vm);
        float va = wa[i]; s_wa[i] = make_float2(va, va);
    }
    if (t < NF_) s_bma[t] = make_float4(bm[t], bm[t], ba[t], ba[t]);
    __syncthreads();

    const int pairId = blockIdx.x * TPB_ + t;     // grid exactly covers PAIRS_TOTAL
    const int b   = pairId >> 15;                 // HW/2 = 32768 pairs per plane
    const int hwp = pairId & 32767;

    // ---- front-end MLP for the 2 pixels of this pair ----
    // Reference semantics per dot: acc = 0; for c ascending: acc = fma(w[c], x[c], acc);
    // then acc += bias (separate rn add); then leaky.
    const size_t exBase = (size_t)b * (EC_ * HW_) + 2 * (size_t)hwp;
    const float2 e0 = *(const float2*)(ex + exBase);
    const float2 e1 = *(const float2*)(ex + exBase + HW_);
    const float2 e2 = *(const float2*)(ex + exBase + 2 * HW_);

    float f1a[NF1_], f1b[NF1_];
#pragma unroll
    for (int i = 0; i < NF1_; i++) {
        float w0 = s_w1[i * 3], wv1 = s_w1[i * 3 + 1], wv2 = s_w1[i * 3 + 2];
        float sx = fmaf(w0, e0.x, 0.0f);
        sx = fmaf(wv1, e1.x, sx);
        sx = fmaf(wv2, e2.x, sx);
        float sy = fmaf(w0, e0.y, 0.0f);
        sy = fmaf(wv1, e1.y, sy);
        sy = fmaf(wv2, e2.y, sy);
        f1a[i] = leaky(__fadd_rn(sx, s_b1[i]));
        f1b[i] = leaky(__fadd_rn(sy, s_b1[i]));
    }

    u64 f2[NF2_];   // fea2 packed (pixelA, pixelB) per channel
#pragma unroll
    for (int i = 0; i < NF2_; i++) {
        float sx = 0.0f, sy = 0.0f;
#pragma unroll
        for (int j = 0; j < NF1_; j++) {   // sequential ascending j — do not split
            float w = s_w2[i * NF1_ + j];
            sx = fmaf(w, f1a[j], sx);
            sy = fmaf(w, f1b[j], sy);
        }
        f2[i] = pk2(leaky(__fadd_rn(sx, s_b2[i])),
                    leaky(__fadd_rn(sy, s_b2[i])));
    }

    // ---- main 64-channel loop: packed dual-head SEQUENTIAL dot products ----
    const size_t chanBase = (size_t)b * (NF_ * HW_) + 2 * (size_t)hwp;
    const float* fmp = fm + chanBase;
    float*       op  = out + chanBase;

#pragma unroll 2
    for (int o = 0; o < NF_; o++) {
        const float2 fv = *(const float2*)(fmp + (size_t)o * HW_);

        const ulonglong2* wmq = (const ulonglong2*)&s_wm[o * NF2_];  // 16B-aligned
        const ulonglong2* waq = (const ulonglong2*)&s_wa[o * NF2_];
        const ulonglong2  bq  = *(const ulonglong2*)&s_bma[o];

        u64 m = 0ull;   // mul head: single sequential chain, ascending c
        u64 a = 0ull;   // add head
#pragma unroll
        for (int j = 0; j < NF2_ / 2; j++) {
            ulonglong2 wmv = wmq[j];
            ulonglong2 wav = waq[j];
            m = fma2(wmv.x, f2[2 * j],     m);
            m = fma2(wmv.y, f2[2 * j + 1], m);
            a = fma2(wav.x, f2[2 * j],     a);
            a = fma2(wav.y, f2[2 * j + 1], a);
        }
        m = add2(m, bq.x);   // bias after the dot (XLA fused-bias order)
        a = add2(a, bq.y);

        float mx, my, ax, ay;
        unpk2(m, mx, my);
        unpk2(a, ax, ay);

        // denom = 1 + fm*mul with explicit rn mul-then-add (no contraction).
        float dx = __fadd_rn(1.0f, __fmul_rn(fv.x, mx));
        float dy = __fadd_rn(1.0f, __fmul_rn(fv.y, my));
        // Division rounding is not pole-amplified (error relative to quotient):
        // __fdividef ~2 ulp is safe against the 1e-3 threshold.
        float ox = __fdividef(ax, dx);
        float oy = __fdividef(ay, dy);

        *(float2*)(op + (size_t)o * HW_) = make_float2(ox, oy);
    }
}

extern "C" void kernel_launch(void* const* d_in, const int* in_sizes, int n_in,
                              void* d_out, int out_size)
{
    const float* fm = (const float*)d_in[0];
    const float* ex = (const float*)d_in[1];
    const float* w1 = (const float*)d_in[2];
    const float* b1 = (const float*)d_in[3];
    const float* w2 = (const float*)d_in[4];
    const float* b2 = (const float*)d_in[5];
    const float* wm = (const float*)d_in[6];
    const float* bm = (const float*)d_in[7];
    const float* wa = (const float*)d_in[8];
    const float* ba = (const float*)d_in[9];
    float* out = (float*)d_out;

    const int blocks = PAIRS_TOTAL / TPB_;   // 2048, exact cover
    attcnn_kernel<<<blocks, TPB_>>>(fm, ex, w1, b1, w2, b2, wm, bm, wa, ba, out);
}

// round 4
// speedup vs baseline: 1.2037x; 1.2037x over previous
#include <cuda_runtime.h>

// Problem constants (AttCnn): B=16, NF=64, EC=3, H=W=256
#define HW_   65536           // H*W
#define B_    16
#define NF_   64
#define EC_   3
#define NF1_  8
#define NF2_  16
#define QUADS_TOTAL (B_ * HW_ / 4)   // 262144 pixel quads (4 consecutive W pixels)
#define TPB_  128

typedef unsigned long long u64;

__device__ __forceinline__ u64 pk2(float x, float y) {
    u64 r; asm("mov.b64 %0, {%1, %2};" : "=l"(r) : "f"(x), "f"(y)); return r;
}
__device__ __forceinline__ void unpk2(u64 p, float& x, float& y) {
    asm("mov.b64 {%0, %1}, %2;" : "=f"(x), "=f"(y) : "l"(p));
}
// Blackwell packed fp32x2 FMA / ADD (sm_103a). Lanewise bit-identical to
// scalar fma.rn.f32 / add.rn.f32 — preserves the verified numerics exactly.
__device__ __forceinline__ u64 fma2(u64 a, u64 b, u64 c) {
    u64 d; asm("fma.rn.f32x2 %0, %1, %2, %3;" : "=l"(d) : "l"(a), "l"(b), "l"(c)); return d;
}
__device__ __forceinline__ u64 add2(u64 a, u64 b) {
    u64 d; asm("add.rn.f32x2 %0, %1, %2;" : "=l"(d) : "l"(a), "l"(b)); return d;
}

__device__ __forceinline__ float leaky(float x) {
    return fmaxf(x, 0.0f) + 0.2f * fminf(x, 0.0f);
}

__global__ void __launch_bounds__(TPB_, 4)
attcnn_kernel(const float* __restrict__ fm,   // [B,NF,H,W]
              const float* __restrict__ ex,   // [B,EC,H,W]
              const float* __restrict__ w1,   // [NF1,EC]
              const float* __restrict__ b1,   // [NF1]
              const float* __restrict__ w2,   // [NF2,NF1]
              const float* __restrict__ b2,   // [NF2]
              const float* __restrict__ wm,   // [NF,NF2]
              const float* __restrict__ bm,   // [NF]
              const float* __restrict__ wa,   // [NF,NF2]
              const float* __restrict__ ba,   // [NF]
              float* __restrict__ out)        // [B,NF,H,W]
{
    // ---- shared weights (full fp32, heads duplicated (w,w) for packed lanes) ----
    __shared__ float s_w1[NF1_ * EC_];
    __shared__ float s_b1[NF1_];
    __shared__ float s_w2[NF2_ * NF1_];
    __shared__ float s_b2[NF2_];
    __shared__ __align__(16) float2 s_wm[NF_ * NF2_];
    __shared__ __align__(16) float2 s_wa[NF_ * NF2_];
    __shared__ __align__(16) float4 s_bma[NF_];         // (bm,bm,ba,ba)

    const int t = threadIdx.x;
    if (t < NF1_ * EC_)  s_w1[t] = w1[t];
    if (t < NF1_)        s_b1[t] = b1[t];
    if (t == 0) { }
    for (int i = t; i < NF2_ * NF1_; i += TPB_) s_w2[i] = w2[i];
    if (t < NF2_)        s_b2[t] = b2[t];
    for (int i = t; i < NF_ * NF2_; i += TPB_) {
        float vm = wm[i]; s_wm[i] = make_float2(vm, vm);
        float va = wa[i]; s_wa[i] = make_float2(va, va);
    }
    if (t < NF_) s_bma[t] = make_float4(bm[t], bm[t], ba[t], ba[t]);
    __syncthreads();

    const int quad = blockIdx.x * TPB_ + t;   // grid exactly covers QUADS_TOTAL
    const int b = quad >> 14;                 // HW/4 = 16384 quads per plane
    const int q = quad & 16383;

    // ---- front-end MLP for the 4 pixels of this quad ----
    // Per-dot semantics (verified): acc=0; ascending c: acc=fma(w[c],x[c],acc);
    // then +bias (separate rn add); then leaky.
    const size_t exBase = (size_t)b * (EC_ * HW_) + 4 * (size_t)q;
    const float4 e0 = *(const float4*)(ex + exBase);
    const float4 e1 = *(const float4*)(ex + exBase + HW_);
    const float4 e2 = *(const float4*)(ex + exBase + 2 * HW_);

    float f10[NF1_], f11[NF1_], f12[NF1_], f13[NF1_];
#pragma unroll
    for (int i = 0; i < NF1_; i++) {
        float w0 = s_w1[i * 3], wv1 = s_w1[i * 3 + 1], wv2 = s_w1[i * 3 + 2];
        float bb = s_b1[i];
        float s0 = fmaf(wv2, e2.x, fmaf(wv1, e1.x, fmaf(w0, e0.x, 0.0f)));
        float s1 = fmaf(wv2, e2.y, fmaf(wv1, e1.y, fmaf(w0, e0.y, 0.0f)));
        float s2 = fmaf(wv2, e2.z, fmaf(wv1, e1.z, fmaf(w0, e0.z, 0.0f)));
        float s3 = fmaf(wv2, e2.w, fmaf(wv1, e1.w, fmaf(w0, e0.w, 0.0f)));
        f10[i] = leaky(__fadd_rn(s0, bb));
        f11[i] = leaky(__fadd_rn(s1, bb));
        f12[i] = leaky(__fadd_rn(s2, bb));
        f13[i] = leaky(__fadd_rn(s3, bb));
    }

    u64 f2lo[NF2_], f2hi[NF2_];   // fea2 packed: lo=(px0,px1), hi=(px2,px3)
#pragma unroll
    for (int i = 0; i < NF2_; i++) {
        float s0 = 0.0f, s1 = 0.0f, s2 = 0.0f, s3 = 0.0f;
#pragma unroll
        for (int j = 0; j < NF1_; j++) {   // sequential ascending j — do not split
            float w = s_w2[i * NF1_ + j];
            s0 = fmaf(w, f10[j], s0);
            s1 = fmaf(w, f11[j], s1);
            s2 = fmaf(w, f12[j], s2);
            s3 = fmaf(w, f13[j], s3);
        }
        float bb = s_b2[i];
        f2lo[i] = pk2(leaky(__fadd_rn(s0, bb)), leaky(__fadd_rn(s1, bb)));
        f2hi[i] = pk2(leaky(__fadd_rn(s2, bb)), leaky(__fadd_rn(s3, bb)));
    }

    // ---- main 64-channel loop, 4-deep fm prefetch ring ----
    const size_t chanBase = (size_t)b * (NF_ * HW_) + 4 * (size_t)q;
    const float* fmp = fm + chanBase;
    float*       op  = out + chanBase;

    float4 buf[4];
#pragma unroll
    for (int i = 0; i < 4; i++) buf[i] = *(const float4*)(fmp + (size_t)i * HW_);

#pragma unroll 4
    for (int o = 0; o < NF_; o++) {
        const float4 fv = buf[o & 3];
        if (o < NF_ - 4)
            buf[o & 3] = *(const float4*)(fmp + (size_t)(o + 4) * HW_);

        const ulonglong2* wmq = (const ulonglong2*)&s_wm[o * NF2_];
        const ulonglong2* waq = (const ulonglong2*)&s_wa[o * NF2_];
        const ulonglong2  bq  = *(const ulonglong2*)&s_bma[o];

        // 4 independent sequential chains (m/a × lo/hi) — order per chain preserved
        u64 mlo = 0ull, mhi = 0ull, alo = 0ull, ahi = 0ull;
#pragma unroll
        for (int j = 0; j < NF2_ / 2; j++) {
            ulonglong2 wmv = wmq[j];
            ulonglong2 wav = waq[j];
            mlo = fma2(wmv.x, f2lo[2 * j],     mlo);
            mlo = fma2(wmv.y, f2lo[2 * j + 1], mlo);
            mhi = fma2(wmv.x, f2hi[2 * j],     mhi);
            mhi = fma2(wmv.y, f2hi[2 * j + 1], mhi);
            alo = fma2(wav.x, f2lo[2 * j],     alo);
            alo = fma2(wav.y, f2lo[2 * j + 1], alo);
            ahi = fma2(wav.x, f2hi[2 * j],     ahi);
            ahi = fma2(wav.y, f2hi[2 * j + 1], ahi);
        }
        mlo = add2(mlo, bq.x);  mhi = add2(mhi, bq.x);   // bias after dot
        alo = add2(alo, bq.y);  ahi = add2(ahi, bq.y);

        float m0, m1, m2, m3, a0, a1, a2, a3;
        unpk2(mlo, m0, m1); unpk2(mhi, m2, m3);
        unpk2(alo, a0, a1); unpk2(ahi, a2, a3);

        // denom = 1 + fm*mul, explicit rn mul-then-add (no contraction)
        float d0 = __fadd_rn(1.0f, __fmul_rn(fv.x, m0));
        float d1 = __fadd_rn(1.0f, __fmul_rn(fv.y, m1));
        float d2 = __fadd_rn(1.0f, __fmul_rn(fv.z, m2));
        float d3 = __fadd_rn(1.0f, __fmul_rn(fv.w, m3));

        float4 ov;
        ov.x = __fdividef(a0, d0);
        ov.y = __fdividef(a1, d1);
        ov.z = __fdividef(a2, d2);
        ov.w = __fdividef(a3, d3);

        *(float4*)(op + (size_t)o * HW_) = ov;
    }
}

extern "C" void kernel_launch(void* const* d_in, const int* in_sizes, int n_in,
                              void* d_out, int out_size)
{
    const float* fm = (const float*)d_in[0];
    const float* ex = (const float*)d_in[1];
    const float* w1 = (const float*)d_in[2];
    const float* b1 = (const float*)d_in[3];
    const float* w2 = (const float*)d_in[4];
    const float* b2 = (const float*)d_in[5];
    const float* wm = (const float*)d_in[6];
    const float* bm = (const float*)d_in[7];
    const float* wa = (const float*)d_in[8];
    const float* ba = (const float*)d_in[9];
    float* out = (float*)d_out;

    const int blocks = QUADS_TOTAL / TPB_;   // 2048, exact cover
    attcnn_kernel<<<blocks, TPB_>>>(fm, ex, w1, b1, w2, b2, wm, bm, wa, ba, out);
}

// round 7
// speedup vs baseline: 1.4518x; 1.2061x over previous
#include <cuda_runtime.h>

// Problem constants (AttCnn): B=16, NF=64, EC=3, H=W=256
#define HW_   65536           // H*W
#define B_    16
#define NF_   64
#define EC_   3
#define NF1_  8
#define NF2_  16
#define QUADS_TOTAL (B_ * HW_ / 4)   // 262144 pixel quads (4 consecutive W pixels)
#define TPB_  128

typedef unsigned long long u64;

__device__ __forceinline__ u64 pk2(float x, float y) {
    u64 r; asm("mov.b64 %0, {%1, %2};" : "=l"(r) : "f"(x), "f"(y)); return r;
}
__device__ __forceinline__ void unpk2(u64 p, float& x, float& y) {
    asm("mov.b64 {%0, %1}, %2;" : "=f"(x), "=f"(y) : "l"(p));
}
// Blackwell packed fp32x2 FMA / ADD (sm_103a). Lanewise bit-identical to
// scalar fma.rn.f32 / add.rn.f32 — preserves the verified numerics exactly.
__device__ __forceinline__ u64 fma2(u64 a, u64 b, u64 c) {
    u64 d; asm("fma.rn.f32x2 %0, %1, %2, %3;" : "=l"(d) : "l"(a), "l"(b), "l"(c)); return d;
}
__device__ __forceinline__ u64 add2(u64 a, u64 b) {
    u64 d; asm("add.rn.f32x2 %0, %1, %2;" : "=l"(d) : "l"(a), "l"(b)); return d;
}

__device__ __forceinline__ void l2_prefetch(const float* p) {
    asm volatile("prefetch.global.L2 [%0];" :: "l"(p));
}
__device__ __forceinline__ void store_cs(float* p, float4 v) {
    asm volatile("st.global.cs.v4.f32 [%0], {%1, %2, %3, %4};"
                 :: "l"(p), "f"(v.x), "f"(v.y), "f"(v.z), "f"(v.w) : "memory");
}

__device__ __forceinline__ float leaky(float x) {
    return fmaxf(x, 0.0f) + 0.2f * fminf(x, 0.0f);
}

__global__ void __launch_bounds__(TPB_, 4)
attcnn_kernel(const float* __restrict__ fm,   // [B,NF,H,W]
              const float* __restrict__ ex,   // [B,EC,H,W]
              const float* __restrict__ w1,   // [NF1,EC]
              const float* __restrict__ b1,   // [NF1]
              const float* __restrict__ w2,   // [NF2,NF1]
              const float* __restrict__ b2,   // [NF2]
              const float* __restrict__ wm,   // [NF,NF2]
              const float* __restrict__ bm,   // [NF]
              const float* __restrict__ wa,   // [NF,NF2]
              const float* __restrict__ ba,   // [NF]
              float* __restrict__ out)        // [B,NF,H,W]
{
    // ---- shared weights (full fp32, heads duplicated (w,w) for packed lanes) ----
    __shared__ float s_w1[NF1_ * EC_];
    __shared__ float s_b1[NF1_];
    __shared__ float s_w2[NF2_ * NF1_];
    __shared__ float s_b2[NF2_];
    __shared__ __align__(16) float2 s_wm[NF_ * NF2_];
    __shared__ __align__(16) float2 s_wa[NF_ * NF2_];
    __shared__ __align__(16) float4 s_bma[NF_];         // (bm,bm,ba,ba)

    const int t = threadIdx.x;
    if (t < NF1_ * EC_)  s_w1[t] = w1[t];
    if (t < NF1_)        s_b1[t] = b1[t];
    for (int i = t; i < NF2_ * NF1_; i += TPB_) s_w2[i] = w2[i];
    if (t < NF2_)        s_b2[t] = b2[t];
    for (int i = t; i < NF_ * NF2_; i += TPB_) {
        float vm = wm[i]; s_wm[i] = make_float2(vm, vm);
        float va = wa[i]; s_wa[i] = make_float2(va, va);
    }
    if (t < NF_) s_bma[t] = make_float4(bm[t], bm[t], ba[t], ba[t]);
    __syncthreads();

    const int quad = blockIdx.x * TPB_ + t;   // grid exactly covers QUADS_TOTAL
    const int b = quad >> 14;                 // HW/4 = 16384 quads per plane
    const int q = quad & 16383;

    const size_t chanBase = (size_t)b * (NF_ * HW_) + 4 * (size_t)q;
    const float* fmp = fm + chanBase;
    float*       op  = out + chanBase;

    // ---- warm the fm stream: ring loads for ch 0..3, L2 prefetch for 4..11 ----
    float4 buf[4];
#pragma unroll
    for (int i = 0; i < 4; i++) buf[i] = *(const float4*)(fmp + (size_t)i * HW_);
#pragma unroll
    for (int i = 4; i < 12; i++) l2_prefetch(fmp + (size_t)i * HW_);

    // ---- front-end MLP for the 4 pixels of this quad ----
    // Verified per-dot semantics: acc=0; ascending c: acc=fma(w[c],x[c],acc);
    // then +bias (separate rn add); then leaky.
    const size_t exBase = (size_t)b * (EC_ * HW_) + 4 * (size_t)q;
    const float4 e0 = *(const float4*)(ex + exBase);
    const float4 e1 = *(const float4*)(ex + exBase + HW_);
    const float4 e2 = *(const float4*)(ex + exBase + 2 * HW_);

    float f10[NF1_], f11[NF1_], f12[NF1_], f13[NF1_];
#pragma unroll
    for (int i = 0; i < NF1_; i++) {
        float w0 = s_w1[i * 3], wv1 = s_w1[i * 3 + 1], wv2 = s_w1[i * 3 + 2];
        float bb = s_b1[i];
        float s0 = fmaf(wv2, e2.x, fmaf(wv1, e1.x, fmaf(w0, e0.x, 0.0f)));
        float s1 = fmaf(wv2, e2.y, fmaf(wv1, e1.y, fmaf(w0, e0.y, 0.0f)));
        float s2 = fmaf(wv2, e2.z, fmaf(wv1, e1.z, fmaf(w0, e0.z, 0.0f)));
        float s3 = fmaf(wv2, e2.w, fmaf(wv1, e1.w, fmaf(w0, e0.w, 0.0f)));
        f10[i] = leaky(__fadd_rn(s0, bb));
        f11[i] = leaky(__fadd_rn(s1, bb));
        f12[i] = leaky(__fadd_rn(s2, bb));
        f13[i] = leaky(__fadd_rn(s3, bb));
    }

    u64 f2lo[NF2_], f2hi[NF2_];   // fea2 packed: lo=(px0,px1), hi=(px2,px3)
#pragma unroll
    for (int i = 0; i < NF2_; i++) {
        float s0 = 0.0f, s1 = 0.0f, s2 = 0.0f, s3 = 0.0f;
#pragma unroll
        for (int j = 0; j < NF1_; j++) {   // sequential ascending j — do not split
            float w = s_w2[i * NF1_ + j];
            s0 = fmaf(w, f10[j], s0);
            s1 = fmaf(w, f11[j], s1);
            s2 = fmaf(w, f12[j], s2);
            s3 = fmaf(w, f13[j], s3);
        }
        float bb = s_b2[i];
        f2lo[i] = pk2(leaky(__fadd_rn(s0, bb)), leaky(__fadd_rn(s1, bb)));
        f2hi[i] = pk2(leaky(__fadd_rn(s2, bb)), leaky(__fadd_rn(s3, bb)));
    }

    // ---- main 64-channel loop: 4-deep LDG ring + L2 prefetch at distance 12 ----
#pragma unroll 4
    for (int o = 0; o < NF_; o++) {
        const float4 fv = buf[o & 3];
        if (o < NF_ - 4)
            buf[o & 3] = *(const float4*)(fmp + (size_t)(o + 4) * HW_);
        if (o + 12 < NF_)
            l2_prefetch(fmp + (size_t)(o + 12) * HW_);

        const ulonglong2* wmq = (const ulonglong2*)&s_wm[o * NF2_];
        const ulonglong2* waq = (const ulonglong2*)&s_wa[o * NF2_];
        const ulonglong2  bq  = *(const ulonglong2*)&s_bma[o];

        // 4 independent sequential chains (m/a × lo/hi) — order per chain preserved
        u64 mlo = 0ull, mhi = 0ull, alo = 0ull, ahi = 0ull;
#pragma unroll
        for (int j = 0; j < NF2_ / 2; j++) {
            ulonglong2 wmv = wmq[j];
            ulonglong2 wav = waq[j];
            mlo = fma2(wmv.x, f2lo[2 * j],     mlo);
            mlo = fma2(wmv.y, f2lo[2 * j + 1], mlo);
            mhi = fma2(wmv.x, f2hi[2 * j],     mhi);
            mhi = fma2(wmv.y, f2hi[2 * j + 1], mhi);
            alo = fma2(wav.x, f2lo[2 * j],     alo);
            alo = fma2(wav.y, f2lo[2 * j + 1], alo);
            ahi = fma2(wav.x, f2hi[2 * j],     ahi);
            ahi = fma2(wav.y, f2hi[2 * j + 1], ahi);
        }
        mlo = add2(mlo, bq.x);  mhi = add2(mhi, bq.x);   // bias after dot
        alo = add2(alo, bq.y);  ahi = add2(ahi, bq.y);

        float m0, m1, m2, m3, a0, a1, a2, a3;
        unpk2(mlo, m0, m1); unpk2(mhi, m2, m3);
        unpk2(alo, a0, a1); unpk2(ahi, a2, a3);

        // denom = 1 + fm*mul, explicit rn mul-then-add (no contraction)
        float d0 = __fadd_rn(1.0f, __fmul_rn(fv.x, m0));
        float d1 = __fadd_rn(1.0f, __fmul_rn(fv.y, m1));
        float d2 = __fadd_rn(1.0f, __fmul_rn(fv.z, m2));
        float d3 = __fadd_rn(1.0f, __fmul_rn(fv.w, m3));

        float4 ov;
        ov.x = __fdividef(a0, d0);
        ov.y = __fdividef(a1, d1);
        ov.z = __fdividef(a2, d2);
        ov.w = __fdividef(a3, d3);

        // streaming store (evict-first) — keeps prefetched fm lines resident in L2
        store_cs(op + (size_t)o * HW_, ov);
    }
}

extern "C" void kernel_launch(void* const* d_in, const int* in_sizes, int n_in,
                              void* d_out, int out_size)
{
    const float* fm = (const float*)d_in[0];
    const float* ex = (const float*)d_in[1];
    const float* w1 = (const float*)d_in[2];
    const float* b1 = (const float*)d_in[3];
    const float* w2 = (const float*)d_in[4];
    const float* b2 = (const float*)d_in[5];
    const float* wm = (const float*)d_in[6];
    const float* bm = (const float*)d_in[7];
    const float* wa = (const float*)d_in[8];
    const float* ba = (const float*)d_in[9];
    float* out = (float*)d_out;

    const int blocks = QUADS_TOTAL / TPB_;   // 2048, exact cover
    attcnn_kernel<<<blocks, TPB_>>>(fm, ex, w1, b1, w2, b2, wm, bm, wa, ba, out);
}